// round 10
// baseline (speedup 1.0000x reference)
#include <cuda_runtime.h>
#include <math.h>
#include <cstdint>

#define N_ROWS 16384
#define K_CB   4096
#define D_DIM  256

__device__ float g_xn[N_ROWS * D_DIM];
__device__ float g_cbn[K_CB * D_DIM];
__device__ signed char g_xa[N_ROWS * D_DIM];
__device__ signed char g_xb[N_ROWS * D_DIM];
__device__ signed char g_ca[K_CB * D_DIM];
__device__ signed char g_cb[K_CB * D_DIM];
__device__ float g_loss_partial[N_ROWS];
__device__ int   g_counts[K_CB];

__device__ __forceinline__ uint32_t smem_u32(const void* p) {
    uint32_t a;
    asm("{ .reg .u64 t; cvta.to.shared.u64 t, %1; cvt.u32.u64 %0, t; }" : "=r"(a) : "l"(p));
    return a;
}

// ===================== reductions ==========================================
__device__ __forceinline__ float block_reduce_sum256(float v, float* sh8) {
    const int t = threadIdx.x;
    #pragma unroll
    for (int o = 16; o > 0; o >>= 1) v += __shfl_xor_sync(0xffffffffu, v, o);
    const int warp = t >> 5, lane = t & 31;
    if (lane == 0) sh8[warp] = v;
    __syncthreads();
    if (warp == 0) {
        float x = (lane < 8) ? sh8[lane] : 0.0f;
        #pragma unroll
        for (int o = 4; o > 0; o >>= 1) x += __shfl_xor_sync(0xffffffffu, x, o);
        if (lane == 0) sh8[0] = x;
    }
    __syncthreads();
    float r = sh8[0];
    __syncthreads();
    return r;
}
__device__ __forceinline__ float block_reduce_max256(float v, float* sh8) {
    const int t = threadIdx.x;
    #pragma unroll
    for (int o = 16; o > 0; o >>= 1) v = fmaxf(v, __shfl_xor_sync(0xffffffffu, v, o));
    const int warp = t >> 5, lane = t & 31;
    if (lane == 0) sh8[warp] = v;
    __syncthreads();
    if (warp == 0) {
        float x = (lane < 8) ? sh8[lane] : -1e30f;
        #pragma unroll
        for (int o = 4; o > 0; o >>= 1) x = fmaxf(x, __shfl_xor_sync(0xffffffffu, x, o));
        if (lane == 0) sh8[0] = x;
    }
    __syncthreads();
    float r = sh8[0];
    __syncthreads();
    return r;
}
__device__ __forceinline__ double block_reduce_sum256_d(double v, double* shd8) {
    const int t = threadIdx.x;
    #pragma unroll
    for (int o = 16; o > 0; o >>= 1) v += __shfl_xor_sync(0xffffffffu, v, o);
    const int warp = t >> 5, lane = t & 31;
    if (lane == 0) shd8[warp] = v;
    __syncthreads();
    if (warp == 0) {
        double x = (lane < 8) ? shd8[lane] : 0.0;
        #pragma unroll
        for (int o = 4; o > 0; o >>= 1) x += __shfl_xor_sync(0xffffffffu, x, o);
        if (lane == 0) shd8[0] = x;
    }
    __syncthreads();
    double r = shd8[0];
    __syncthreads();
    return r;
}

// ===================== normalize + fixed-point split =======================
__device__ __forceinline__ void quant_split(float q, signed char* pa, signed char* pb) {
    int X = __float2int_rn(q * 32768.0f);
    X = max(-32640, min(32639, X));
    const int a = (X + 128) >> 8;          // a in [-127,127]
    const int b = X - (a << 8);            // b in [-128,127], X = 256a + b exactly
    *pa = (signed char)a;
    *pb = (signed char)b;
}

__global__ void normalize_cb_kernel(const float* __restrict__ in) {
    __shared__ float sh[8];
    const int row = blockIdx.x, t = threadIdx.x;
    const float v = in[row * D_DIM + t];
    const float ss = block_reduce_sum256(v * v, sh);
    const float q = v / fmaxf(sqrtf(ss), 1e-12f);
    g_cbn[row * D_DIM + t] = q;
    quant_split(q, &g_ca[row * D_DIM + t], &g_cb[row * D_DIM + t]);
    if (t == 0) g_counts[row] = 0;
}
__global__ void normalize_x_kernel(const float* __restrict__ in) {
    __shared__ float sh[8];
    const int row = blockIdx.x, t = threadIdx.x;
    const float v = in[row * D_DIM + t];
    const float ss = block_reduce_sum256(v * v, sh);
    const float q = v / fmaxf(sqrtf(ss), 1e-12f);
    g_xn[row * D_DIM + t] = q;
    quant_split(q, &g_xa[row * D_DIM + t], &g_xb[row * D_DIM + t]);
}

// ===================== int8 fixed-point IMMA GEMM ==========================
// x ~= X/2^15, X = 256a+b. dot*2^30 = 65536*Saa + 256*Scross + Sbb (exact).
// logit = 20*dot - 20. CTA 128x128, 8 warps (2M x 4N), warp 64x32,
// 32 BK=32 chunks (4 sub-GEMM phases x 8), 3-stage cp.async ring.
#define SROW 48                        // padded smem row stride (bytes)
#define TILE_B (128 * SROW)            // 6144
#define STAGE_B (2 * TILE_B)           // 12288
#define NCHUNK 32

__device__ __forceinline__ void cp16(uint32_t saddr, const void* gptr) {
    asm volatile("cp.async.cg.shared.global [%0], [%1], 16;"
                 :: "r"(saddr), "l"(__cvta_generic_to_global(gptr)));
}

__global__ __launch_bounds__(256, 1)
void gemm_tc_kernel(float* __restrict__ C) {
    __shared__ signed char sm[3 * STAGE_B];
    const uint32_t sbase = smem_u32(sm);

    const int t = threadIdx.x;
    const int wid = t >> 5, lane = t & 31;
    const int g = lane >> 2, tig = lane & 3;
    const int warpM = wid & 1;
    const int warpN = wid >> 1;
    const int m0 = blockIdx.y << 7;
    const int n0 = blockIdx.x << 7;

    const int lsel = lane & 15;
    const int ksel16 = (lane >> 4) << 4;   // byte offset 0 or 16

    int   acc[4][4][4];
    float fm[4][4][4];
    #pragma unroll
    for (int i = 0; i < 4; i++)
        #pragma unroll
        for (int j = 0; j < 4; j++)
            #pragma unroll
            for (int c = 0; c < 4; c++) { acc[i][j][c] = 0; fm[i][j][c] = 0.0f; }

    // loader mapping: thread t -> A chunk (row t>>1, half t&1) + same for B
    const int lrow = t >> 1, lsub = (t & 1) << 4;

    auto issue_stage = [&](int stage, int c) {
        // chunk c -> sources: c<16 uses xa else xb; B uses cb on chunks 8-15,24-31
        const signed char* Asrc = (c < 16) ? g_xa : g_xb;
        const signed char* Bsrc = ((c >> 3) & 1) ? g_cb : g_ca;
        const int d0 = (c & 7) << 5;
        const uint32_t sa = sbase + stage * STAGE_B;
        const uint32_t sb = sa + TILE_B;
        cp16(sa + lrow * SROW + lsub, Asrc + (size_t)(m0 + lrow) * D_DIM + d0 + lsub);
        cp16(sb + lrow * SROW + lsub, Bsrc + (size_t)(n0 + lrow) * D_DIM + d0 + lsub);
        asm volatile("cp.async.commit_group;");
    };

    issue_stage(0, 0);
    issue_stage(1, 1);

    #pragma unroll 1
    for (int kt = 0; kt < NCHUNK; kt++) {
        if (kt < NCHUNK - 1) asm volatile("cp.async.wait_group 1;");
        else                 asm volatile("cp.async.wait_group 0;");
        __syncthreads();

        const int stage = kt - (kt / 3) * 3;
        const uint32_t sa = sbase + stage * STAGE_B;
        const uint32_t sb = sa + TILE_B;

        uint32_t af[4][4], bfr[4][2];
        #pragma unroll
        for (int mt = 0; mt < 4; mt++) {
            const uint32_t aaddr = sa + (warpM * 64 + mt * 16 + lsel) * SROW + ksel16;
            asm volatile(
                "ldmatrix.sync.aligned.m8n8.x4.shared.b16 {%0,%1,%2,%3}, [%4];"
                : "=r"(af[mt][0]), "=r"(af[mt][1]), "=r"(af[mt][2]), "=r"(af[mt][3])
                : "r"(aaddr));
        }
        #pragma unroll
        for (int np = 0; np < 2; np++) {
            const uint32_t baddr = sb + (warpN * 32 + np * 16 + lsel) * SROW + ksel16;
            asm volatile(
                "ldmatrix.sync.aligned.m8n8.x4.shared.b16 {%0,%1,%2,%3}, [%4];"
                : "=r"(bfr[2 * np][0]), "=r"(bfr[2 * np + 1][0]),
                  "=r"(bfr[2 * np][1]), "=r"(bfr[2 * np + 1][1])
                : "r"(baddr));
        }
        #pragma unroll
        for (int mt = 0; mt < 4; mt++)
            #pragma unroll
            for (int nt = 0; nt < 4; nt++)
                asm volatile(
                    "mma.sync.aligned.m16n8k32.row.col.s32.s8.s8.s32 "
                    "{%0,%1,%2,%3}, {%4,%5,%6,%7}, {%8,%9}, {%0,%1,%2,%3};"
                    : "+r"(acc[mt][nt][0]), "+r"(acc[mt][nt][1]),
                      "+r"(acc[mt][nt][2]), "+r"(acc[mt][nt][3])
                    : "r"(af[mt][0]), "r"(af[mt][1]), "r"(af[mt][2]), "r"(af[mt][3]),
                      "r"(bfr[nt][0]), "r"(bfr[nt][1]));

        // phase drains (exact s32->f32 converts, |S| < 2^23)
        if (kt == 7 || kt == 23 || kt == NCHUNK - 1) {
            const float s = (kt == 7) ? 6.103515625e-05f        // 2^-14
                          : (kt == 23) ? 2.384185791015625e-07f // 2^-22
                          : 9.313225746154785e-10f;             // 2^-30
            #pragma unroll
            for (int mt = 0; mt < 4; mt++)
                #pragma unroll
                for (int nt = 0; nt < 4; nt++)
                    #pragma unroll
                    for (int c = 0; c < 4; c++) {
                        fm[mt][nt][c] = fmaf((float)acc[mt][nt][c], s, fm[mt][nt][c]);
                        acc[mt][nt][c] = 0;
                    }
        }

        if (kt < NCHUNK - 2) {
            const int ns = (kt + 2) - ((kt + 2) / 3) * 3;
            issue_stage(ns, kt + 2);
        }
    }

    // epilogue: scalar paired stores (C region is only 4B-aligned)
    #pragma unroll
    for (int mt = 0; mt < 4; mt++) {
        #pragma unroll
        for (int nt = 0; nt < 4; nt++) {
            const int r  = m0 + warpM * 64 + mt * 16 + g;
            const int cc = n0 + warpN * 32 + nt * 8 + tig * 2;
            float* p0 = C + (size_t)r * K_CB + cc;
            float* p1 = C + (size_t)(r + 8) * K_CB + cc;
            p0[0] = fmaf(20.0f, fm[mt][nt][0], -20.0f);
            p0[1] = fmaf(20.0f, fm[mt][nt][1], -20.0f);
            p1[0] = fmaf(20.0f, fm[mt][nt][2], -20.0f);
            p1[1] = fmaf(20.0f, fm[mt][nt][3], -20.0f);
        }
    }
}

// ===================== softmax / argmin / gather ===========================
#define MAX_CAND 64

__global__ __launch_bounds__(256)
void softmax_row_kernel(float* __restrict__ probs,
                        float* __restrict__ quant,
                        float* __restrict__ idx_out) {
    __shared__ float  xrow[256];
    __shared__ float  sh8[8];
    __shared__ double shd8[8];
    __shared__ int    cand[MAX_CAND];
    __shared__ double cdist[MAX_CAND];
    __shared__ int    ncand;
    __shared__ int    ridx_sh;

    const int n = blockIdx.x, t = threadIdx.x;
    float* row = probs + (size_t)n * K_CB;

    xrow[t] = g_xn[n * D_DIM + t];
    if (t == 0) ncand = 0;

    float lv[16];
    float best = -1e30f;
    #pragma unroll
    for (int i = 0; i < 16; i++) {
        lv[i] = row[t + (i << 8)];
        best = fmaxf(best, lv[i]);
    }
    __syncthreads();
    const float rmax = block_reduce_max256(best, sh8);

    const float thresh = rmax - 3e-3f;   // >> int8 quantization logit noise
    #pragma unroll
    for (int i = 0; i < 16; i++) {
        if (lv[i] >= thresh) {
            const int p = atomicAdd(&ncand, 1);
            if (p < MAX_CAND) cand[p] = t + (i << 8);
        }
    }
    __syncthreads();
    const int nc = min(ncand, MAX_CAND);

    for (int c = 0; c < nc; c++) {
        const int k = cand[c];
        const double prod = (double)xrow[t] * (double)g_cbn[(size_t)k * D_DIM + t];
        const double s = block_reduce_sum256_d(prod, shd8);
        if (t == 0) cdist[c] = 2.0 - 2.0 * s;
    }
    __syncthreads();

    if (t == 0) {
        double dmin = 1e30;
        for (int c = 0; c < nc; c++) dmin = fmin(dmin, cdist[c]);
        int bi = 0x7fffffff;
        for (int c = 0; c < nc; c++)
            if (cdist[c] <= dmin + 4e-7) bi = min(bi, cand[c]);
        ridx_sh = bi;
    }

    float ssum = 0.0f;
    #pragma unroll
    for (int i = 0; i < 16; i++) {
        lv[i] = __expf(lv[i] - rmax);
        ssum += lv[i];
    }
    const float tot = block_reduce_sum256(ssum, sh8);
    const float inv = 1.0f / tot;
    #pragma unroll
    for (int i = 0; i < 16; i++) row[t + (i << 8)] = lv[i] * inv;

    const int ridx = ridx_sh;
    const float xv = xrow[t];
    const float cv = g_cbn[(size_t)ridx * D_DIM + t];
    quant[(size_t)n * D_DIM + t] = xv + (cv - xv);
    const float d = cv - xv;
    const float lp = block_reduce_sum256(d * d, sh8);
    if (t == 0) {
        g_loss_partial[n] = lp;
        atomicAdd(&g_counts[ridx], 1);
        idx_out[n] = (float)ridx;
    }
}

// ===================== finalize ============================================
__global__ void finalize_kernel(float* __restrict__ out_loss,
                                float* __restrict__ out_perp) {
    __shared__ float sh[8];
    const int t = threadIdx.x;
    float s = 0.0f;
    for (int i = t; i < N_ROWS; i += 256) s += g_loss_partial[i];
    const float tot = block_reduce_sum256(s, sh);

    float e = 0.0f;
    for (int i = t; i < K_CB; i += 256) {
        const float p = (float)g_counts[i] / (float)N_ROWS;
        e += p * logf(p + 1e-10f);
    }
    const float esum = block_reduce_sum256(e, sh);

    if (t == 0) {
        *out_loss = 0.25f * (tot / (float)((size_t)N_ROWS * D_DIM));
        *out_perp = expf(-esum);
    }
}

// ===========================================================================
extern "C" void kernel_launch(void* const* d_in, const int* in_sizes, int n_in,
                              void* d_out, int out_size) {
    const float* inputs   = (const float*)d_in[0];
    const float* codebook = (const float*)d_in[1];

    float* out       = (float*)d_out;
    float* out_loss  = out;
    float* out_quant = out + 1;
    float* out_probs = out_quant + (size_t)N_ROWS * D_DIM;
    float* out_perp  = out_probs + (size_t)N_ROWS * K_CB;
    float* out_idx   = out_perp + 1;

    normalize_cb_kernel<<<K_CB, 256>>>(codebook);
    normalize_x_kernel<<<N_ROWS, 256>>>(inputs);

    dim3 grid(K_CB / 128, N_ROWS / 128);   // (32, 128)
    gemm_tc_kernel<<<grid, 256>>>(out_probs);

    softmax_row_kernel<<<N_ROWS, 256>>>(out_probs, out_quant, out_idx);
    finalize_kernel<<<1, 256>>>(out_loss, out_perp);
}

// round 11
// speedup vs baseline: 2.1583x; 2.1583x over previous
#include <cuda_runtime.h>
#include <cuda_bf16.h>
#include <math.h>
#include <cstdint>

#define N_ROWS 16384
#define K_CB   4096
#define D_DIM  256

__device__ float g_xn[N_ROWS * D_DIM];
__device__ float g_cbn[K_CB * D_DIM];
__device__ __nv_bfloat16 g_xh[N_ROWS * D_DIM];
__device__ __nv_bfloat16 g_xl[N_ROWS * D_DIM];
__device__ __nv_bfloat16 g_cbh[K_CB * D_DIM];
__device__ __nv_bfloat16 g_cbl[K_CB * D_DIM];
__device__ float g_loss_partial[N_ROWS];
__device__ int   g_counts[K_CB];

__device__ __forceinline__ uint32_t smem_u32(const void* p) {
    uint32_t a;
    asm("{ .reg .u64 t; cvta.to.shared.u64 t, %1; cvt.u32.u64 %0, t; }" : "=r"(a) : "l"(p));
    return a;
}

// ===================== reductions ==========================================
__device__ __forceinline__ float block_reduce_sum256(float v, float* sh8) {
    const int t = threadIdx.x;
    #pragma unroll
    for (int o = 16; o > 0; o >>= 1) v += __shfl_xor_sync(0xffffffffu, v, o);
    const int warp = t >> 5, lane = t & 31;
    if (lane == 0) sh8[warp] = v;
    __syncthreads();
    if (warp == 0) {
        float x = (lane < 8) ? sh8[lane] : 0.0f;
        #pragma unroll
        for (int o = 4; o > 0; o >>= 1) x += __shfl_xor_sync(0xffffffffu, x, o);
        if (lane == 0) sh8[0] = x;
    }
    __syncthreads();
    float r = sh8[0];
    __syncthreads();
    return r;
}
__device__ __forceinline__ float block_reduce_max256(float v, float* sh8) {
    const int t = threadIdx.x;
    #pragma unroll
    for (int o = 16; o > 0; o >>= 1) v = fmaxf(v, __shfl_xor_sync(0xffffffffu, v, o));
    const int warp = t >> 5, lane = t & 31;
    if (lane == 0) sh8[warp] = v;
    __syncthreads();
    if (warp == 0) {
        float x = (lane < 8) ? sh8[lane] : -1e30f;
        #pragma unroll
        for (int o = 4; o > 0; o >>= 1) x = fmaxf(x, __shfl_xor_sync(0xffffffffu, x, o));
        if (lane == 0) sh8[0] = x;
    }
    __syncthreads();
    float r = sh8[0];
    __syncthreads();
    return r;
}
__device__ __forceinline__ double block_reduce_sum256_d(double v, double* shd8) {
    const int t = threadIdx.x;
    #pragma unroll
    for (int o = 16; o > 0; o >>= 1) v += __shfl_xor_sync(0xffffffffu, v, o);
    const int warp = t >> 5, lane = t & 31;
    if (lane == 0) shd8[warp] = v;
    __syncthreads();
    if (warp == 0) {
        double x = (lane < 8) ? shd8[lane] : 0.0;
        #pragma unroll
        for (int o = 4; o > 0; o >>= 1) x += __shfl_xor_sync(0xffffffffu, x, o);
        if (lane == 0) shd8[0] = x;
    }
    __syncthreads();
    double r = shd8[0];
    __syncthreads();
    return r;
}

// ===================== normalize + bf16 split (fused) ======================
__global__ void normalize_all_kernel(const float* __restrict__ inputs,
                                     const float* __restrict__ codebook) {
    __shared__ float sh[8];
    const int b = blockIdx.x, t = threadIdx.x;
    const bool is_cb = (b < K_CB);
    const int row = is_cb ? b : (b - K_CB);
    const float* src = is_cb ? codebook : inputs;
    const float v = src[row * D_DIM + t];
    const float ss = block_reduce_sum256(v * v, sh);
    const float q = v / fmaxf(sqrtf(ss), 1e-12f);
    const __nv_bfloat16 h = __float2bfloat16(q);
    const __nv_bfloat16 l = __float2bfloat16(q - __bfloat162float(h));
    if (is_cb) {
        g_cbn[row * D_DIM + t] = q;
        g_cbh[row * D_DIM + t] = h;
        g_cbl[row * D_DIM + t] = l;
        if (t == 0) g_counts[row] = 0;
    } else {
        g_xn[row * D_DIM + t] = q;
        g_xh[row * D_DIM + t] = h;
        g_xl[row * D_DIM + t] = l;
    }
}

// ===================== cp.async pipelined split-bf16 GEMM ==================
// logits[m,n] = 20*(xh·cbh + xh·cbl + xl·cbh) - 20
// CTA 128x128, 8 warps (2M x 4N), warp tile 64x32, 3-stage cp.async ring,
// 24 BK=32 chunks (3 phases x 8), ONE sync/iter, 2 CTAs/SM.
#define SA 40                              // bf16 row stride (80 B)
#define TILE_B (128 * SA * 2)              // 10240
#define STAGE_B (2 * TILE_B)               // 20480
#define GEMM_SMEM (3 * STAGE_B)            // 61440

__device__ __forceinline__ void cp16(uint32_t saddr, const void* gptr) {
    asm volatile("cp.async.cg.shared.global [%0], [%1], 16;"
                 :: "r"(saddr), "l"(__cvta_generic_to_global(gptr)));
}

__global__ __launch_bounds__(256, 2)
void gemm_tc_kernel(float* __restrict__ C) {
    extern __shared__ char sm[];
    const uint32_t sbase = smem_u32(sm);

    const int t = threadIdx.x;
    const int wid = t >> 5, lane = t & 31;
    const int g = lane >> 2, tig = lane & 3;
    const int warpM = wid & 1;
    const int warpN = wid >> 1;
    const int m0 = blockIdx.y << 7;
    const int n0 = blockIdx.x << 7;

    const int lsel = lane & 15;
    const int ksel = (lane >> 4) << 3;

    float acc[4][4][4];
    #pragma unroll
    for (int i = 0; i < 4; i++)
        #pragma unroll
        for (int j = 0; j < 4; j++)
            #pragma unroll
            for (int c = 0; c < 4; c++) acc[i][j][c] = 0.0f;

    auto issue_stage = [&](int stage, int kt) {
        const int phase = kt >> 3;
        const int d0 = (kt & 7) << 5;
        const __nv_bfloat16* Asrc = (phase == 2) ? g_xl  : g_xh;
        const __nv_bfloat16* Bsrc = (phase == 1) ? g_cbl : g_cbh;
        const uint32_t sa = sbase + stage * STAGE_B;
        const uint32_t sb = sa + TILE_B;
        #pragma unroll
        for (int j = 0; j < 2; j++) {
            const int c = t + (j << 8);          // 0..511
            const int row = c >> 2, sub = c & 3; // 32 bf16/row = 4 x 16B
            cp16(sa + row * (SA * 2) + sub * 16,
                 Asrc + (size_t)(m0 + row) * D_DIM + d0 + sub * 8);
            cp16(sb + row * (SA * 2) + sub * 16,
                 Bsrc + (size_t)(n0 + row) * D_DIM + d0 + sub * 8);
        }
        asm volatile("cp.async.commit_group;");
    };

    issue_stage(0, 0);
    issue_stage(1, 1);

    #pragma unroll 1
    for (int kt = 0; kt < 24; kt++) {
        if (kt < 23) asm volatile("cp.async.wait_group 1;");
        else         asm volatile("cp.async.wait_group 0;");
        __syncthreads();   // single barrier per iteration

        // issue next stage first (writes stage (kt+2)%3 == (kt-1)%3, whose
        // readers all finished before the barrier above)
        if (kt < 22) {
            const int ns = (kt + 2) - ((kt + 2) / 3) * 3;
            issue_stage(ns, kt + 2);
        }

        const int stage = kt - (kt / 3) * 3;
        const uint32_t sa = sbase + stage * STAGE_B;
        const uint32_t sb = sa + TILE_B;

        #pragma unroll
        for (int k0 = 0; k0 < 32; k0 += 16) {
            uint32_t af[4][4], bfr[4][2];
            #pragma unroll
            for (int mt = 0; mt < 4; mt++) {
                const uint32_t aaddr = sa
                    + (warpM * 64 + mt * 16 + lsel) * (SA * 2) + (k0 + ksel) * 2;
                asm volatile(
                    "ldmatrix.sync.aligned.m8n8.x4.shared.b16 {%0,%1,%2,%3}, [%4];"
                    : "=r"(af[mt][0]), "=r"(af[mt][1]), "=r"(af[mt][2]), "=r"(af[mt][3])
                    : "r"(aaddr));
            }
            #pragma unroll
            for (int np = 0; np < 2; np++) {
                const uint32_t baddr = sb
                    + (warpN * 32 + np * 16 + lsel) * (SA * 2) + (k0 + ksel) * 2;
                asm volatile(
                    "ldmatrix.sync.aligned.m8n8.x4.shared.b16 {%0,%1,%2,%3}, [%4];"
                    : "=r"(bfr[2 * np][0]), "=r"(bfr[2 * np + 1][0]),
                      "=r"(bfr[2 * np][1]), "=r"(bfr[2 * np + 1][1])
                    : "r"(baddr));
            }
            #pragma unroll
            for (int mt = 0; mt < 4; mt++)
                #pragma unroll
                for (int nt = 0; nt < 4; nt++)
                    asm volatile(
                        "mma.sync.aligned.m16n8k16.row.col.f32.bf16.bf16.f32 "
                        "{%0,%1,%2,%3}, {%4,%5,%6,%7}, {%8,%9}, {%0,%1,%2,%3};"
                        : "+f"(acc[mt][nt][0]), "+f"(acc[mt][nt][1]),
                          "+f"(acc[mt][nt][2]), "+f"(acc[mt][nt][3])
                        : "r"(af[mt][0]), "r"(af[mt][1]), "r"(af[mt][2]), "r"(af[mt][3]),
                          "r"(bfr[nt][0]), "r"(bfr[nt][1]));
        }
    }

    // epilogue: scalar paired stores (C region is only 4B-aligned)
    #pragma unroll
    for (int mt = 0; mt < 4; mt++) {
        #pragma unroll
        for (int nt = 0; nt < 4; nt++) {
            const int r  = m0 + warpM * 64 + mt * 16 + g;
            const int cc = n0 + warpN * 32 + nt * 8 + tig * 2;
            float* p0 = C + (size_t)r * K_CB + cc;
            float* p1 = C + (size_t)(r + 8) * K_CB + cc;
            p0[0] = fmaf(20.0f, acc[mt][nt][0], -20.0f);
            p0[1] = fmaf(20.0f, acc[mt][nt][1], -20.0f);
            p1[0] = fmaf(20.0f, acc[mt][nt][2], -20.0f);
            p1[1] = fmaf(20.0f, acc[mt][nt][3], -20.0f);
        }
    }
}

// ===================== softmax / argmin / gather ===========================
#define MAX_CAND 64

__global__ __launch_bounds__(256)
void softmax_row_kernel(float* __restrict__ probs,
                        float* __restrict__ quant,
                        float* __restrict__ idx_out) {
    __shared__ float  xrow[256];
    __shared__ float  sh8[8];
    __shared__ double shd8[8];
    __shared__ int    cand[MAX_CAND];
    __shared__ double cdist[MAX_CAND];
    __shared__ int    ncand;
    __shared__ int    ridx_sh;

    const int n = blockIdx.x, t = threadIdx.x;
    float* row = probs + (size_t)n * K_CB;

    xrow[t] = g_xn[n * D_DIM + t];
    if (t == 0) ncand = 0;

    float lv[16];
    float best = -1e30f;
    #pragma unroll
    for (int i = 0; i < 16; i++) {
        lv[i] = row[t + (i << 8)];
        best = fmaxf(best, lv[i]);
    }
    __syncthreads();
    const float rmax = block_reduce_max256(best, sh8);

    const float thresh = rmax - 1e-3f;   // >> split-bf16 GEMM noise
    #pragma unroll
    for (int i = 0; i < 16; i++) {
        if (lv[i] >= thresh) {
            const int p = atomicAdd(&ncand, 1);
            if (p < MAX_CAND) cand[p] = t + (i << 8);
        }
    }
    __syncthreads();
    const int nc = min(ncand, MAX_CAND);

    for (int c = 0; c < nc; c++) {
        const int k = cand[c];
        const double prod = (double)xrow[t] * (double)g_cbn[(size_t)k * D_DIM + t];
        const double s = block_reduce_sum256_d(prod, shd8);
        if (t == 0) cdist[c] = 2.0 - 2.0 * s;
    }
    __syncthreads();

    if (t == 0) {
        double dmin = 1e30;
        for (int c = 0; c < nc; c++) dmin = fmin(dmin, cdist[c]);
        int bi = 0x7fffffff;
        for (int c = 0; c < nc; c++)
            if (cdist[c] <= dmin + 4e-7) bi = min(bi, cand[c]);
        ridx_sh = bi;
    }

    float ssum = 0.0f;
    #pragma unroll
    for (int i = 0; i < 16; i++) {
        lv[i] = __expf(lv[i] - rmax);
        ssum += lv[i];
    }
    const float tot = block_reduce_sum256(ssum, sh8);
    const float inv = 1.0f / tot;
    #pragma unroll
    for (int i = 0; i < 16; i++) row[t + (i << 8)] = lv[i] * inv;

    const int ridx = ridx_sh;
    const float xv = xrow[t];
    const float cv = g_cbn[(size_t)ridx * D_DIM + t];
    quant[(size_t)n * D_DIM + t] = xv + (cv - xv);
    const float d = cv - xv;
    const float lp = block_reduce_sum256(d * d, sh8);
    if (t == 0) {
        g_loss_partial[n] = lp;
        atomicAdd(&g_counts[ridx], 1);
        idx_out[n] = (float)ridx;
    }
}

// ===================== finalize ============================================
__global__ void finalize_kernel(float* __restrict__ out_loss,
                                float* __restrict__ out_perp) {
    __shared__ float sh[8];
    const int t = threadIdx.x;
    float s = 0.0f;
    for (int i = t; i < N_ROWS; i += 256) s += g_loss_partial[i];
    const float tot = block_reduce_sum256(s, sh);

    float e = 0.0f;
    for (int i = t; i < K_CB; i += 256) {
        const float p = (float)g_counts[i] / (float)N_ROWS;
        e += p * logf(p + 1e-10f);
    }
    const float esum = block_reduce_sum256(e, sh);

    if (t == 0) {
        *out_loss = 0.25f * (tot / (float)((size_t)N_ROWS * D_DIM));
        *out_perp = expf(-esum);
    }
}

// ===========================================================================
extern "C" void kernel_launch(void* const* d_in, const int* in_sizes, int n_in,
                              void* d_out, int out_size) {
    const float* inputs   = (const float*)d_in[0];
    const float* codebook = (const float*)d_in[1];

    float* out       = (float*)d_out;
    float* out_loss  = out;
    float* out_quant = out + 1;
    float* out_probs = out_quant + (size_t)N_ROWS * D_DIM;
    float* out_perp  = out_probs + (size_t)N_ROWS * K_CB;
    float* out_idx   = out_perp + 1;

    cudaFuncSetAttribute(gemm_tc_kernel,
                         cudaFuncAttributeMaxDynamicSharedMemorySize, GEMM_SMEM);

    normalize_all_kernel<<<K_CB + N_ROWS, 256>>>(inputs, codebook);

    dim3 grid(K_CB / 128, N_ROWS / 128);   // (32, 128)
    gemm_tc_kernel<<<grid, 256, GEMM_SMEM>>>(out_probs);

    softmax_row_kernel<<<N_ROWS, 256>>>(out_probs, out_quant, out_idx);
    finalize_kernel<<<1, 256>>>(out_loss, out_perp);
}

// round 12
// speedup vs baseline: 2.5224x; 1.1687x over previous
#include <cuda_runtime.h>
#include <cuda_bf16.h>
#include <math.h>
#include <cstdint>

#define N_ROWS 16384
#define K_CB   4096
#define D_DIM  256

__device__ float g_xn[N_ROWS * D_DIM];
__device__ float g_cbn[K_CB * D_DIM];
__device__ __nv_bfloat16 g_xh[N_ROWS * D_DIM];
__device__ __nv_bfloat16 g_xl[N_ROWS * D_DIM];
__device__ __nv_bfloat16 g_cbh[K_CB * D_DIM];
__device__ __nv_bfloat16 g_cbl[K_CB * D_DIM];
__device__ __align__(16) float g_logits[(size_t)N_ROWS * K_CB];   // aligned scratch
__device__ float g_loss_partial[N_ROWS];
__device__ int   g_counts[K_CB];

__device__ __forceinline__ uint32_t smem_u32(const void* p) {
    uint32_t a;
    asm("{ .reg .u64 t; cvta.to.shared.u64 t, %1; cvt.u32.u64 %0, t; }" : "=r"(a) : "l"(p));
    return a;
}

// ===================== reductions ==========================================
__device__ __forceinline__ float block_reduce_sum256(float v, float* sh8) {
    const int t = threadIdx.x;
    #pragma unroll
    for (int o = 16; o > 0; o >>= 1) v += __shfl_xor_sync(0xffffffffu, v, o);
    const int warp = t >> 5, lane = t & 31;
    if (lane == 0) sh8[warp] = v;
    __syncthreads();
    if (warp == 0) {
        float x = (lane < 8) ? sh8[lane] : 0.0f;
        #pragma unroll
        for (int o = 4; o > 0; o >>= 1) x += __shfl_xor_sync(0xffffffffu, x, o);
        if (lane == 0) sh8[0] = x;
    }
    __syncthreads();
    float r = sh8[0];
    __syncthreads();
    return r;
}
__device__ __forceinline__ float block_reduce_max256(float v, float* sh8) {
    const int t = threadIdx.x;
    #pragma unroll
    for (int o = 16; o > 0; o >>= 1) v = fmaxf(v, __shfl_xor_sync(0xffffffffu, v, o));
    const int warp = t >> 5, lane = t & 31;
    if (lane == 0) sh8[warp] = v;
    __syncthreads();
    if (warp == 0) {
        float x = (lane < 8) ? sh8[lane] : -1e30f;
        #pragma unroll
        for (int o = 4; o > 0; o >>= 1) x = fmaxf(x, __shfl_xor_sync(0xffffffffu, x, o));
        if (lane == 0) sh8[0] = x;
    }
    __syncthreads();
    float r = sh8[0];
    __syncthreads();
    return r;
}
__device__ __forceinline__ double block_reduce_sum256_d(double v, double* shd8) {
    const int t = threadIdx.x;
    #pragma unroll
    for (int o = 16; o > 0; o >>= 1) v += __shfl_xor_sync(0xffffffffu, v, o);
    const int warp = t >> 5, lane = t & 31;
    if (lane == 0) shd8[warp] = v;
    __syncthreads();
    if (warp == 0) {
        double x = (lane < 8) ? shd8[lane] : 0.0;
        #pragma unroll
        for (int o = 4; o > 0; o >>= 1) x += __shfl_xor_sync(0xffffffffu, x, o);
        if (lane == 0) shd8[0] = x;
    }
    __syncthreads();
    double r = shd8[0];
    __syncthreads();
    return r;
}
__device__ __forceinline__ float block_reduce_sum1024(float v, float* sh32) {
    const int t = threadIdx.x;
    #pragma unroll
    for (int o = 16; o > 0; o >>= 1) v += __shfl_xor_sync(0xffffffffu, v, o);
    const int warp = t >> 5, lane = t & 31;
    if (lane == 0) sh32[warp] = v;
    __syncthreads();
    if (warp == 0) {
        float x = sh32[lane];
        #pragma unroll
        for (int o = 16; o > 0; o >>= 1) x += __shfl_xor_sync(0xffffffffu, x, o);
        if (lane == 0) sh32[0] = x;
    }
    __syncthreads();
    float r = sh32[0];
    __syncthreads();
    return r;
}

// ===================== normalize + bf16 split (fused) ======================
__global__ void normalize_all_kernel(const float* __restrict__ inputs,
                                     const float* __restrict__ codebook) {
    __shared__ float sh[8];
    const int b = blockIdx.x, t = threadIdx.x;
    const bool is_cb = (b < K_CB);
    const int row = is_cb ? b : (b - K_CB);
    const float* src = is_cb ? codebook : inputs;
    const float v = src[row * D_DIM + t];
    const float ss = block_reduce_sum256(v * v, sh);
    const float q = v / fmaxf(sqrtf(ss), 1e-12f);
    const __nv_bfloat16 h = __float2bfloat16(q);
    const __nv_bfloat16 l = __float2bfloat16(q - __bfloat162float(h));
    if (is_cb) {
        g_cbn[row * D_DIM + t] = q;
        g_cbh[row * D_DIM + t] = h;
        g_cbl[row * D_DIM + t] = l;
        if (t == 0) g_counts[row] = 0;
    } else {
        g_xn[row * D_DIM + t] = q;
        g_xh[row * D_DIM + t] = h;
        g_xl[row * D_DIM + t] = l;
    }
}

// ===================== cp.async pipelined split-bf16 GEMM ==================
// logits[m,n] = 20*(xh·cbh + xh·cbl + xl·cbh) - 20, written to g_logits.
// CTA 128x128, 8 warps (2M x 4N), warp tile 64x32, 3-stage cp.async ring,
// 12 BK=64 chunks (3 phases x 4), ONE sync/iter, 2 CTAs/SM.
#define SA 72                              // bf16 row stride (144 B)
#define TILE_B (128 * SA * 2)              // 18432
#define STAGE_B (2 * TILE_B)               // 36864
#define GEMM_SMEM (3 * STAGE_B)            // 110592

__device__ __forceinline__ void cp16(uint32_t saddr, const void* gptr) {
    asm volatile("cp.async.cg.shared.global [%0], [%1], 16;"
                 :: "r"(saddr), "l"(__cvta_generic_to_global(gptr)));
}

__global__ __launch_bounds__(256, 2)
void gemm_tc_kernel(float* __restrict__ Cout) {
    extern __shared__ char sm[];
    const uint32_t sbase = smem_u32(sm);

    const int t = threadIdx.x;
    const int wid = t >> 5, lane = t & 31;
    const int g = lane >> 2, tig = lane & 3;
    const int warpM = wid & 1;
    const int warpN = wid >> 1;
    const int m0 = blockIdx.y << 7;
    const int n0 = blockIdx.x << 7;

    const int lsel = lane & 15;
    const int ksel = (lane >> 4) << 3;

    float acc[4][4][4];
    #pragma unroll
    for (int i = 0; i < 4; i++)
        #pragma unroll
        for (int j = 0; j < 4; j++)
            #pragma unroll
            for (int c = 0; c < 4; c++) acc[i][j][c] = 0.0f;

    auto issue_stage = [&](int stage, int kt) {
        const int phase = kt >> 2;           // 0:hh 1:h*l 2:l*h
        const int d0 = (kt & 3) << 6;        // 0,64,128,192
        const __nv_bfloat16* Asrc = (phase == 2) ? g_xl  : g_xh;
        const __nv_bfloat16* Bsrc = (phase == 1) ? g_cbl : g_cbh;
        const uint32_t sa = sbase + stage * STAGE_B;
        const uint32_t sb = sa + TILE_B;
        #pragma unroll
        for (int j = 0; j < 4; j++) {
            const int c = t + (j << 8);          // 0..1023
            const int row = c >> 3, sub = c & 7; // 64 bf16/row = 8 x 16B
            cp16(sa + row * (SA * 2) + sub * 16,
                 Asrc + (size_t)(m0 + row) * D_DIM + d0 + sub * 8);
            cp16(sb + row * (SA * 2) + sub * 16,
                 Bsrc + (size_t)(n0 + row) * D_DIM + d0 + sub * 8);
        }
        asm volatile("cp.async.commit_group;");
    };

    issue_stage(0, 0);
    issue_stage(1, 1);

    #pragma unroll 1
    for (int kt = 0; kt < 12; kt++) {
        if (kt < 11) asm volatile("cp.async.wait_group 1;");
        else         asm volatile("cp.async.wait_group 0;");
        __syncthreads();   // single barrier per iteration

        if (kt < 10) {
            const int ns = (kt + 2) - ((kt + 2) / 3) * 3;
            issue_stage(ns, kt + 2);
        }

        const int stage = kt - (kt / 3) * 3;
        const uint32_t sa = sbase + stage * STAGE_B;
        const uint32_t sb = sa + TILE_B;

        #pragma unroll
        for (int k0 = 0; k0 < 64; k0 += 16) {
            uint32_t af[4][4], bfr[4][2];
            #pragma unroll
            for (int mt = 0; mt < 4; mt++) {
                const uint32_t aaddr = sa
                    + (warpM * 64 + mt * 16 + lsel) * (SA * 2) + (k0 + ksel) * 2;
                asm volatile(
                    "ldmatrix.sync.aligned.m8n8.x4.shared.b16 {%0,%1,%2,%3}, [%4];"
                    : "=r"(af[mt][0]), "=r"(af[mt][1]), "=r"(af[mt][2]), "=r"(af[mt][3])
                    : "r"(aaddr));
            }
            #pragma unroll
            for (int np = 0; np < 2; np++) {
                const uint32_t baddr = sb
                    + (warpN * 32 + np * 16 + lsel) * (SA * 2) + (k0 + ksel) * 2;
                asm volatile(
                    "ldmatrix.sync.aligned.m8n8.x4.shared.b16 {%0,%1,%2,%3}, [%4];"
                    : "=r"(bfr[2 * np][0]), "=r"(bfr[2 * np + 1][0]),
                      "=r"(bfr[2 * np][1]), "=r"(bfr[2 * np + 1][1])
                    : "r"(baddr));
            }
            #pragma unroll
            for (int mt = 0; mt < 4; mt++)
                #pragma unroll
                for (int nt = 0; nt < 4; nt++)
                    asm volatile(
                        "mma.sync.aligned.m16n8k16.row.col.f32.bf16.bf16.f32 "
                        "{%0,%1,%2,%3}, {%4,%5,%6,%7}, {%8,%9}, {%0,%1,%2,%3};"
                        : "+f"(acc[mt][nt][0]), "+f"(acc[mt][nt][1]),
                          "+f"(acc[mt][nt][2]), "+f"(acc[mt][nt][3])
                        : "r"(af[mt][0]), "r"(af[mt][1]), "r"(af[mt][2]), "r"(af[mt][3]),
                          "r"(bfr[nt][0]), "r"(bfr[nt][1]));
        }
    }

    // epilogue: float2 stores into aligned g_logits
    #pragma unroll
    for (int mt = 0; mt < 4; mt++) {
        #pragma unroll
        for (int nt = 0; nt < 4; nt++) {
            const int r  = m0 + warpM * 64 + mt * 16 + g;
            const int cc = n0 + warpN * 32 + nt * 8 + tig * 2;
            float2 v0, v1;
            v0.x = fmaf(20.0f, acc[mt][nt][0], -20.0f);
            v0.y = fmaf(20.0f, acc[mt][nt][1], -20.0f);
            v1.x = fmaf(20.0f, acc[mt][nt][2], -20.0f);
            v1.y = fmaf(20.0f, acc[mt][nt][3], -20.0f);
            *(float2*)(g_logits + (size_t)r * K_CB + cc)       = v0;
            *(float2*)(g_logits + (size_t)(r + 8) * K_CB + cc) = v1;
        }
    }
    (void)Cout;
}

// ===================== softmax / argmin / gather ===========================
#define MAX_CAND 64

__global__ __launch_bounds__(256)
void softmax_row_kernel(float* __restrict__ probs,
                        float* __restrict__ quant,
                        float* __restrict__ idx_out) {
    __shared__ float  xrow[256];
    __shared__ float  sh8[8];
    __shared__ double shd8[8];
    __shared__ int    cand[MAX_CAND];
    __shared__ double cdist[MAX_CAND];
    __shared__ int    ncand;
    __shared__ int    ridx_sh;

    const int n = blockIdx.x, t = threadIdx.x;
    const float* lrow = g_logits + (size_t)n * K_CB;
    float* prow = probs + (size_t)n * K_CB;

    xrow[t] = g_xn[n * D_DIM + t];
    if (t == 0) ncand = 0;

    // vectorized logit loads: thread t covers cols 4t..4t+3 (+1024 strides)
    float lv[16];
    float best = -1e30f;
    #pragma unroll
    for (int i = 0; i < 4; i++) {
        const float4 v = *(const float4*)(lrow + (t << 2) + (i << 10));
        lv[4 * i + 0] = v.x; lv[4 * i + 1] = v.y;
        lv[4 * i + 2] = v.z; lv[4 * i + 3] = v.w;
        best = fmaxf(fmaxf(fmaxf(v.x, v.y), fmaxf(v.z, v.w)), best);
    }
    __syncthreads();
    const float rmax = block_reduce_max256(best, sh8);

    const float thresh = rmax - 1e-3f;   // >> split-bf16 GEMM noise
    #pragma unroll
    for (int i = 0; i < 16; i++) {
        if (lv[i] >= thresh) {
            const int p = atomicAdd(&ncand, 1);
            if (p < MAX_CAND) cand[p] = (t << 2) + ((i >> 2) << 10) + (i & 3);
        }
    }
    __syncthreads();
    const int nc = min(ncand, MAX_CAND);

    for (int c = 0; c < nc; c++) {
        const int k = cand[c];
        const double prod = (double)xrow[t] * (double)g_cbn[(size_t)k * D_DIM + t];
        const double s = block_reduce_sum256_d(prod, shd8);
        if (t == 0) cdist[c] = 2.0 - 2.0 * s;
    }
    __syncthreads();

    if (t == 0) {
        double dmin = 1e30;
        for (int c = 0; c < nc; c++) dmin = fmin(dmin, cdist[c]);
        int bi = 0x7fffffff;
        for (int c = 0; c < nc; c++)
            if (cdist[c] <= dmin + 4e-7) bi = min(bi, cand[c]);
        ridx_sh = bi;
    }

    float ssum = 0.0f;
    #pragma unroll
    for (int i = 0; i < 16; i++) {
        lv[i] = __expf(lv[i] - rmax);
        ssum += lv[i];
    }
    const float tot = block_reduce_sum256(ssum, sh8);
    const float inv = 1.0f / tot;
    #pragma unroll
    for (int i = 0; i < 16; i++)
        prow[(t << 2) + ((i >> 2) << 10) + (i & 3)] = lv[i] * inv;

    const int ridx = ridx_sh;
    const float xv = xrow[t];
    const float cv = g_cbn[(size_t)ridx * D_DIM + t];
    quant[(size_t)n * D_DIM + t] = xv + (cv - xv);
    const float d = cv - xv;
    const float lp = block_reduce_sum256(d * d, sh8);
    if (t == 0) {
        g_loss_partial[n] = lp;
        atomicAdd(&g_counts[ridx], 1);
        idx_out[n] = (float)ridx;
    }
}

// ===================== finalize ============================================
__global__ __launch_bounds__(1024)
void finalize_kernel(float* __restrict__ out_loss,
                     float* __restrict__ out_perp) {
    __shared__ float sh32[32];
    const int t = threadIdx.x;
    float s = 0.0f;
    #pragma unroll
    for (int i = 0; i < 4; i++) {
        const float4 v = *(const float4*)(g_loss_partial + (t << 2) + (i << 12));
        s += (v.x + v.y) + (v.z + v.w);
    }
    const float tot = block_reduce_sum1024(s, sh32);

    float e = 0.0f;
    const int4 cv = *(const int4*)(g_counts + (t << 2));
    const float invN = 1.0f / (float)N_ROWS;
    {
        const float p0 = (float)cv.x * invN, p1 = (float)cv.y * invN;
        const float p2 = (float)cv.z * invN, p3 = (float)cv.w * invN;
        e = p0 * logf(p0 + 1e-10f) + p1 * logf(p1 + 1e-10f)
          + p2 * logf(p2 + 1e-10f) + p3 * logf(p3 + 1e-10f);
    }
    const float esum = block_reduce_sum1024(e, sh32);

    if (t == 0) {
        *out_loss = 0.25f * (tot / (float)((size_t)N_ROWS * D_DIM));
        *out_perp = expf(-esum);
    }
}

// ===========================================================================
extern "C" void kernel_launch(void* const* d_in, const int* in_sizes, int n_in,
                              void* d_out, int out_size) {
    const float* inputs   = (const float*)d_in[0];
    const float* codebook = (const float*)d_in[1];

    float* out       = (float*)d_out;
    float* out_loss  = out;
    float* out_quant = out + 1;
    float* out_probs = out_quant + (size_t)N_ROWS * D_DIM;
    float* out_perp  = out_probs + (size_t)N_ROWS * K_CB;
    float* out_idx   = out_perp + 1;

    cudaFuncSetAttribute(gemm_tc_kernel,
                         cudaFuncAttributeMaxDynamicSharedMemorySize, GEMM_SMEM);

    normalize_all_kernel<<<K_CB + N_ROWS, 256>>>(inputs, codebook);

    dim3 grid(K_CB / 128, N_ROWS / 128);   // (32, 128)
    gemm_tc_kernel<<<grid, 256, GEMM_SMEM>>>(out_probs);

    softmax_row_kernel<<<N_ROWS, 256>>>(out_probs, out_quant, out_idx);
    finalize_kernel<<<1, 1024>>>(out_loss, out_perp);
}

// round 13
// speedup vs baseline: 2.7131x; 1.0756x over previous
#include <cuda_runtime.h>
#include <cuda_bf16.h>
#include <math.h>
#include <cstdint>

#define N_ROWS 16384
#define K_CB   4096
#define D_DIM  256

__device__ float g_xn[N_ROWS * D_DIM];
__device__ float g_cbn[K_CB * D_DIM];
__device__ __nv_bfloat16 g_xh[N_ROWS * D_DIM];
__device__ __nv_bfloat16 g_xl[N_ROWS * D_DIM];
__device__ __nv_bfloat16 g_cbh[K_CB * D_DIM];
__device__ __nv_bfloat16 g_cbl[K_CB * D_DIM];
__device__ __align__(16) float g_logits[(size_t)N_ROWS * K_CB];   // aligned scratch
__device__ float g_loss_partial[N_ROWS];
__device__ int   g_counts[K_CB];

__device__ __forceinline__ uint32_t smem_u32(const void* p) {
    uint32_t a;
    asm("{ .reg .u64 t; cvta.to.shared.u64 t, %1; cvt.u32.u64 %0, t; }" : "=r"(a) : "l"(p));
    return a;
}

// ===================== reductions ==========================================
__device__ __forceinline__ float block_reduce_sum256(float v, float* sh8) {
    const int t = threadIdx.x;
    #pragma unroll
    for (int o = 16; o > 0; o >>= 1) v += __shfl_xor_sync(0xffffffffu, v, o);
    const int warp = t >> 5, lane = t & 31;
    if (lane == 0) sh8[warp] = v;
    __syncthreads();
    if (warp == 0) {
        float x = (lane < 8) ? sh8[lane] : 0.0f;
        #pragma unroll
        for (int o = 4; o > 0; o >>= 1) x += __shfl_xor_sync(0xffffffffu, x, o);
        if (lane == 0) sh8[0] = x;
    }
    __syncthreads();
    float r = sh8[0];
    __syncthreads();
    return r;
}
// joint max+sum reduce, one barrier set for both
__device__ __forceinline__ void block_reduce_maxsum256(float m, float s,
                                                       float* shm, float* shs,
                                                       float* out_m, float* out_s) {
    const int t = threadIdx.x;
    #pragma unroll
    for (int o = 16; o > 0; o >>= 1) {
        m = fmaxf(m, __shfl_xor_sync(0xffffffffu, m, o));
        s += __shfl_xor_sync(0xffffffffu, s, o);
    }
    const int warp = t >> 5, lane = t & 31;
    if (lane == 0) { shm[warp] = m; shs[warp] = s; }
    __syncthreads();
    if (warp == 0) {
        float xm = (lane < 8) ? shm[lane] : -1e30f;
        float xs = (lane < 8) ? shs[lane] : 0.0f;
        #pragma unroll
        for (int o = 4; o > 0; o >>= 1) {
            xm = fmaxf(xm, __shfl_xor_sync(0xffffffffu, xm, o));
            xs += __shfl_xor_sync(0xffffffffu, xs, o);
        }
        if (lane == 0) { shm[0] = xm; shs[0] = xs; }
    }
    __syncthreads();
    *out_m = shm[0];
    *out_s = shs[0];
    __syncthreads();
}
__device__ __forceinline__ double block_reduce_sum256_d(double v, double* shd8) {
    const int t = threadIdx.x;
    #pragma unroll
    for (int o = 16; o > 0; o >>= 1) v += __shfl_xor_sync(0xffffffffu, v, o);
    const int warp = t >> 5, lane = t & 31;
    if (lane == 0) shd8[warp] = v;
    __syncthreads();
    if (warp == 0) {
        double x = (lane < 8) ? shd8[lane] : 0.0;
        #pragma unroll
        for (int o = 4; o > 0; o >>= 1) x += __shfl_xor_sync(0xffffffffu, x, o);
        if (lane == 0) shd8[0] = x;
    }
    __syncthreads();
    double r = shd8[0];
    __syncthreads();
    return r;
}
__device__ __forceinline__ float block_reduce_sum1024(float v, float* sh32) {
    const int t = threadIdx.x;
    #pragma unroll
    for (int o = 16; o > 0; o >>= 1) v += __shfl_xor_sync(0xffffffffu, v, o);
    const int warp = t >> 5, lane = t & 31;
    if (lane == 0) sh32[warp] = v;
    __syncthreads();
    if (warp == 0) {
        float x = sh32[lane];
        #pragma unroll
        for (int o = 16; o > 0; o >>= 1) x += __shfl_xor_sync(0xffffffffu, x, o);
        if (lane == 0) sh32[0] = x;
    }
    __syncthreads();
    float r = sh32[0];
    __syncthreads();
    return r;
}

// ===================== normalize + bf16 split (fused) ======================
__global__ void normalize_all_kernel(const float* __restrict__ inputs,
                                     const float* __restrict__ codebook) {
    __shared__ float sh[8];
    const int b = blockIdx.x, t = threadIdx.x;
    const bool is_cb = (b < K_CB);
    const int row = is_cb ? b : (b - K_CB);
    const float* src = is_cb ? codebook : inputs;
    const float v = src[row * D_DIM + t];
    const float ss = block_reduce_sum256(v * v, sh);
    const float q = v / fmaxf(sqrtf(ss), 1e-12f);
    const __nv_bfloat16 h = __float2bfloat16(q);
    const __nv_bfloat16 l = __float2bfloat16(q - __bfloat162float(h));
    if (is_cb) {
        g_cbn[row * D_DIM + t] = q;
        g_cbh[row * D_DIM + t] = h;
        g_cbl[row * D_DIM + t] = l;
        if (t == 0) g_counts[row] = 0;
    } else {
        g_xn[row * D_DIM + t] = q;
        g_xh[row * D_DIM + t] = h;
        g_xl[row * D_DIM + t] = l;
    }
}

// ===================== cp.async pipelined split-bf16 GEMM ==================
// logits[m,n] = 20*(xh·cbh + xh·cbl + xl·cbh) - 20, written to g_logits.
// CTA 128x128, 8 warps (2M x 4N), warp tile 64x32, 3-stage cp.async ring,
// 12 BK=64 chunks (3 phases x 4), ONE sync/iter, 2 CTAs/SM.
#define SA 72                              // bf16 row stride (144 B)
#define TILE_B (128 * SA * 2)              // 18432
#define STAGE_B (2 * TILE_B)               // 36864
#define GEMM_SMEM (3 * STAGE_B)            // 110592

__device__ __forceinline__ void cp16(uint32_t saddr, const void* gptr) {
    asm volatile("cp.async.cg.shared.global [%0], [%1], 16;"
                 :: "r"(saddr), "l"(__cvta_generic_to_global(gptr)));
}

__global__ __launch_bounds__(256, 2)
void gemm_tc_kernel(float* __restrict__ Cout) {
    extern __shared__ char sm[];
    const uint32_t sbase = smem_u32(sm);

    const int t = threadIdx.x;
    const int wid = t >> 5, lane = t & 31;
    const int g = lane >> 2, tig = lane & 3;
    const int warpM = wid & 1;
    const int warpN = wid >> 1;
    const int m0 = blockIdx.y << 7;
    const int n0 = blockIdx.x << 7;

    const int lsel = lane & 15;
    const int ksel = (lane >> 4) << 3;

    float acc[4][4][4];
    #pragma unroll
    for (int i = 0; i < 4; i++)
        #pragma unroll
        for (int j = 0; j < 4; j++)
            #pragma unroll
            for (int c = 0; c < 4; c++) acc[i][j][c] = 0.0f;

    auto issue_stage = [&](int stage, int kt) {
        const int phase = kt >> 2;           // 0:hh 1:h*l 2:l*h
        const int d0 = (kt & 3) << 6;        // 0,64,128,192
        const __nv_bfloat16* Asrc = (phase == 2) ? g_xl  : g_xh;
        const __nv_bfloat16* Bsrc = (phase == 1) ? g_cbl : g_cbh;
        const uint32_t sa = sbase + stage * STAGE_B;
        const uint32_t sb = sa + TILE_B;
        #pragma unroll
        for (int j = 0; j < 4; j++) {
            const int c = t + (j << 8);          // 0..1023
            const int row = c >> 3, sub = c & 7; // 64 bf16/row = 8 x 16B
            cp16(sa + row * (SA * 2) + sub * 16,
                 Asrc + (size_t)(m0 + row) * D_DIM + d0 + sub * 8);
            cp16(sb + row * (SA * 2) + sub * 16,
                 Bsrc + (size_t)(n0 + row) * D_DIM + d0 + sub * 8);
        }
        asm volatile("cp.async.commit_group;");
    };

    issue_stage(0, 0);
    issue_stage(1, 1);

    #pragma unroll 1
    for (int kt = 0; kt < 12; kt++) {
        if (kt < 11) asm volatile("cp.async.wait_group 1;");
        else         asm volatile("cp.async.wait_group 0;");
        __syncthreads();   // single barrier per iteration

        if (kt < 10) {
            const int ns = (kt + 2) - ((kt + 2) / 3) * 3;
            issue_stage(ns, kt + 2);
        }

        const int stage = kt - (kt / 3) * 3;
        const uint32_t sa = sbase + stage * STAGE_B;
        const uint32_t sb = sa + TILE_B;

        #pragma unroll
        for (int k0 = 0; k0 < 64; k0 += 16) {
            uint32_t af[4][4], bfr[4][2];
            #pragma unroll
            for (int mt = 0; mt < 4; mt++) {
                const uint32_t aaddr = sa
                    + (warpM * 64 + mt * 16 + lsel) * (SA * 2) + (k0 + ksel) * 2;
                asm volatile(
                    "ldmatrix.sync.aligned.m8n8.x4.shared.b16 {%0,%1,%2,%3}, [%4];"
                    : "=r"(af[mt][0]), "=r"(af[mt][1]), "=r"(af[mt][2]), "=r"(af[mt][3])
                    : "r"(aaddr));
            }
            #pragma unroll
            for (int np = 0; np < 2; np++) {
                const uint32_t baddr = sb
                    + (warpN * 32 + np * 16 + lsel) * (SA * 2) + (k0 + ksel) * 2;
                asm volatile(
                    "ldmatrix.sync.aligned.m8n8.x4.shared.b16 {%0,%1,%2,%3}, [%4];"
                    : "=r"(bfr[2 * np][0]), "=r"(bfr[2 * np + 1][0]),
                      "=r"(bfr[2 * np][1]), "=r"(bfr[2 * np + 1][1])
                    : "r"(baddr));
            }
            #pragma unroll
            for (int mt = 0; mt < 4; mt++)
                #pragma unroll
                for (int nt = 0; nt < 4; nt++)
                    asm volatile(
                        "mma.sync.aligned.m16n8k16.row.col.f32.bf16.bf16.f32 "
                        "{%0,%1,%2,%3}, {%4,%5,%6,%7}, {%8,%9}, {%0,%1,%2,%3};"
                        : "+f"(acc[mt][nt][0]), "+f"(acc[mt][nt][1]),
                          "+f"(acc[mt][nt][2]), "+f"(acc[mt][nt][3])
                        : "r"(af[mt][0]), "r"(af[mt][1]), "r"(af[mt][2]), "r"(af[mt][3]),
                          "r"(bfr[nt][0]), "r"(bfr[nt][1]));
        }
    }

    // epilogue: float2 stores into aligned g_logits
    #pragma unroll
    for (int mt = 0; mt < 4; mt++) {
        #pragma unroll
        for (int nt = 0; nt < 4; nt++) {
            const int r  = m0 + warpM * 64 + mt * 16 + g;
            const int cc = n0 + warpN * 32 + nt * 8 + tig * 2;
            float2 v0, v1;
            v0.x = fmaf(20.0f, acc[mt][nt][0], -20.0f);
            v0.y = fmaf(20.0f, acc[mt][nt][1], -20.0f);
            v1.x = fmaf(20.0f, acc[mt][nt][2], -20.0f);
            v1.y = fmaf(20.0f, acc[mt][nt][3], -20.0f);
            *(float2*)(g_logits + (size_t)r * K_CB + cc)       = v0;
            *(float2*)(g_logits + (size_t)(r + 8) * K_CB + cc) = v1;
        }
    }
    (void)Cout;
}

// ===================== softmax / argmin / gather ===========================
// logits <= 0 always (dist >= 0), so exp(l) in [e-40, 1]: no max-subtraction
// needed for range safety. probs = exp(l)/sum(exp(l)) == softmax(l).
#define MAX_CAND 64

__global__ __launch_bounds__(256)
void softmax_row_kernel(float* __restrict__ probs,
                        float* __restrict__ quant,
                        float* __restrict__ idx_out) {
    __shared__ float  xrow[256];
    __shared__ float  shm[8], shs[8];
    __shared__ double shd8[8];
    __shared__ int    cand[MAX_CAND];
    __shared__ double cdist[MAX_CAND];
    __shared__ int    ncand;
    __shared__ int    ridx_sh;

    const int n = blockIdx.x, t = threadIdx.x;
    const float* lrow = g_logits + (size_t)n * K_CB;
    float* prow = probs + (size_t)n * K_CB;

    xrow[t] = g_xn[n * D_DIM + t];
    if (t == 0) ncand = 0;

    // load + exp immediately; track local max(exp) and sum(exp)
    float ev[16];
    float emax = 0.0f, esum = 0.0f;
    #pragma unroll
    for (int i = 0; i < 4; i++) {
        const float4 v = *(const float4*)(lrow + (t << 2) + (i << 10));
        const float e0 = __expf(v.x), e1 = __expf(v.y);
        const float e2 = __expf(v.z), e3 = __expf(v.w);
        ev[4 * i + 0] = e0; ev[4 * i + 1] = e1;
        ev[4 * i + 2] = e2; ev[4 * i + 3] = e3;
        emax = fmaxf(fmaxf(fmaxf(e0, e1), fmaxf(e2, e3)), emax);
        esum += (e0 + e1) + (e2 + e3);
    }
    float evmax, tot;
    block_reduce_maxsum256(emax, esum, shm, shs, &evmax, &tot);

    // write probs immediately (stores retire asynchronously)
    const float inv = 1.0f / tot;
    #pragma unroll
    for (int i = 0; i < 16; i++)
        prow[(t << 2) + ((i >> 2) << 10) + (i & 3)] = ev[i] * inv;

    // candidates in exp domain: ev >= evmax*exp(-1e-3) (threshold slightly
    // widened to 0.999; rescore below resolves exactly)
    const float cthresh = evmax * 0.999f;
    #pragma unroll
    for (int i = 0; i < 16; i++) {
        if (ev[i] >= cthresh) {
            const int p = atomicAdd(&ncand, 1);
            if (p < MAX_CAND) cand[p] = (t << 2) + ((i >> 2) << 10) + (i & 3);
        }
    }
    __syncthreads();
    const int nc = min(ncand, MAX_CAND);

    for (int c = 0; c < nc; c++) {
        const int k = cand[c];
        const double prod = (double)xrow[t] * (double)g_cbn[(size_t)k * D_DIM + t];
        const double s = block_reduce_sum256_d(prod, shd8);
        if (t == 0) cdist[c] = 2.0 - 2.0 * s;
    }
    __syncthreads();

    if (t == 0) {
        double dmin = 1e30;
        for (int c = 0; c < nc; c++) dmin = fmin(dmin, cdist[c]);
        int bi = 0x7fffffff;
        for (int c = 0; c < nc; c++)
            if (cdist[c] <= dmin + 4e-7) bi = min(bi, cand[c]);
        ridx_sh = bi;
    }
    __syncthreads();

    const int ridx = ridx_sh;
    const float xv = xrow[t];
    const float cv = g_cbn[(size_t)ridx * D_DIM + t];
    quant[(size_t)n * D_DIM + t] = xv + (cv - xv);
    const float d = cv - xv;
    const float lp = block_reduce_sum256(d * d, shm);
    if (t == 0) {
        g_loss_partial[n] = lp;
        atomicAdd(&g_counts[ridx], 1);
        idx_out[n] = (float)ridx;
    }
}

// ===================== finalize ============================================
__global__ __launch_bounds__(1024)
void finalize_kernel(float* __restrict__ out_loss,
                     float* __restrict__ out_perp) {
    __shared__ float sh32[32];
    const int t = threadIdx.x;
    float s = 0.0f;
    #pragma unroll
    for (int i = 0; i < 4; i++) {
        const float4 v = *(const float4*)(g_loss_partial + (t << 2) + (i << 12));
        s += (v.x + v.y) + (v.z + v.w);
    }
    const float tot = block_reduce_sum1024(s, sh32);

    float e = 0.0f;
    const int4 cv = *(const int4*)(g_counts + (t << 2));
    const float invN = 1.0f / (float)N_ROWS;
    {
        const float p0 = (float)cv.x * invN, p1 = (float)cv.y * invN;
        const float p2 = (float)cv.z * invN, p3 = (float)cv.w * invN;
        e = p0 * logf(p0 + 1e-10f) + p1 * logf(p1 + 1e-10f)
          + p2 * logf(p2 + 1e-10f) + p3 * logf(p3 + 1e-10f);
    }
    const float esum = block_reduce_sum1024(e, sh32);

    if (t == 0) {
        *out_loss = 0.25f * (tot / (float)((size_t)N_ROWS * D_DIM));
        *out_perp = expf(-esum);
    }
}

// ===========================================================================
extern "C" void kernel_launch(void* const* d_in, const int* in_sizes, int n_in,
                              void* d_out, int out_size) {
    const float* inputs   = (const float*)d_in[0];
    const float* codebook = (const float*)d_in[1];

    float* out       = (float*)d_out;
    float* out_loss  = out;
    float* out_quant = out + 1;
    float* out_probs = out_quant + (size_t)N_ROWS * D_DIM;
    float* out_perp  = out_probs + (size_t)N_ROWS * K_CB;
    float* out_idx   = out_perp + 1;

    cudaFuncSetAttribute(gemm_tc_kernel,
                         cudaFuncAttributeMaxDynamicSharedMemorySize, GEMM_SMEM);

    normalize_all_kernel<<<K_CB + N_ROWS, 256>>>(inputs, codebook);

    dim3 grid(K_CB / 128, N_ROWS / 128);   // (32, 128)
    gemm_tc_kernel<<<grid, 256, GEMM_SMEM>>>(out_probs);

    softmax_row_kernel<<<N_ROWS, 256>>>(out_probs, out_quant, out_idx);
    finalize_kernel<<<1, 1024>>>(out_loss, out_perp);
}

// round 14
// speedup vs baseline: 2.7455x; 1.0119x over previous
#include <cuda_runtime.h>
#include <cuda_bf16.h>
#include <math.h>
#include <cstdint>

#define N_ROWS 16384
#define K_CB   4096
#define D_DIM  256

__device__ float g_xn[N_ROWS * D_DIM];
__device__ float g_cbn[K_CB * D_DIM];
__device__ __nv_bfloat16 g_xh[N_ROWS * D_DIM];
__device__ __nv_bfloat16 g_xl[N_ROWS * D_DIM];
__device__ __nv_bfloat16 g_cbh[K_CB * D_DIM];
__device__ __nv_bfloat16 g_cbl[K_CB * D_DIM];
__device__ __align__(16) float g_logits[(size_t)N_ROWS * K_CB];   // holds exp(logit)
__device__ float g_loss_partial[N_ROWS];
__device__ int   g_counts[K_CB];

__device__ __forceinline__ uint32_t smem_u32(const void* p) {
    uint32_t a;
    asm("{ .reg .u64 t; cvta.to.shared.u64 t, %1; cvt.u32.u64 %0, t; }" : "=r"(a) : "l"(p));
    return a;
}

// ===================== reductions ==========================================
__device__ __forceinline__ float block_reduce_sum256(float v, float* sh8) {
    const int t = threadIdx.x;
    #pragma unroll
    for (int o = 16; o > 0; o >>= 1) v += __shfl_xor_sync(0xffffffffu, v, o);
    const int warp = t >> 5, lane = t & 31;
    if (lane == 0) sh8[warp] = v;
    __syncthreads();
    if (warp == 0) {
        float x = (lane < 8) ? sh8[lane] : 0.0f;
        #pragma unroll
        for (int o = 4; o > 0; o >>= 1) x += __shfl_xor_sync(0xffffffffu, x, o);
        if (lane == 0) sh8[0] = x;
    }
    __syncthreads();
    float r = sh8[0];
    __syncthreads();
    return r;
}
__device__ __forceinline__ void block_reduce_maxsum256(float m, float s,
                                                       float* shm, float* shs,
                                                       float* out_m, float* out_s) {
    const int t = threadIdx.x;
    #pragma unroll
    for (int o = 16; o > 0; o >>= 1) {
        m = fmaxf(m, __shfl_xor_sync(0xffffffffu, m, o));
        s += __shfl_xor_sync(0xffffffffu, s, o);
    }
    const int warp = t >> 5, lane = t & 31;
    if (lane == 0) { shm[warp] = m; shs[warp] = s; }
    __syncthreads();
    if (warp == 0) {
        float xm = (lane < 8) ? shm[lane] : -1e30f;
        float xs = (lane < 8) ? shs[lane] : 0.0f;
        #pragma unroll
        for (int o = 4; o > 0; o >>= 1) {
            xm = fmaxf(xm, __shfl_xor_sync(0xffffffffu, xm, o));
            xs += __shfl_xor_sync(0xffffffffu, xs, o);
        }
        if (lane == 0) { shm[0] = xm; shs[0] = xs; }
    }
    __syncthreads();
    *out_m = shm[0];
    *out_s = shs[0];
    __syncthreads();
}
__device__ __forceinline__ double block_reduce_sum256_d(double v, double* shd8) {
    const int t = threadIdx.x;
    #pragma unroll
    for (int o = 16; o > 0; o >>= 1) v += __shfl_xor_sync(0xffffffffu, v, o);
    const int warp = t >> 5, lane = t & 31;
    if (lane == 0) shd8[warp] = v;
    __syncthreads();
    if (warp == 0) {
        double x = (lane < 8) ? shd8[lane] : 0.0;
        #pragma unroll
        for (int o = 4; o > 0; o >>= 1) x += __shfl_xor_sync(0xffffffffu, x, o);
        if (lane == 0) shd8[0] = x;
    }
    __syncthreads();
    double r = shd8[0];
    __syncthreads();
    return r;
}
__device__ __forceinline__ float block_reduce_sum1024(float v, float* sh32) {
    const int t = threadIdx.x;
    #pragma unroll
    for (int o = 16; o > 0; o >>= 1) v += __shfl_xor_sync(0xffffffffu, v, o);
    const int warp = t >> 5, lane = t & 31;
    if (lane == 0) sh32[warp] = v;
    __syncthreads();
    if (warp == 0) {
        float x = sh32[lane];
        #pragma unroll
        for (int o = 16; o > 0; o >>= 1) x += __shfl_xor_sync(0xffffffffu, x, o);
        if (lane == 0) sh32[0] = x;
    }
    __syncthreads();
    float r = sh32[0];
    __syncthreads();
    return r;
}

// ===================== normalize: warp-per-row, no block barriers ==========
// 256 threads = 8 warps = 8 rows/block; lane covers 8 elems (2x float4).
__global__ __launch_bounds__(256)
void normalize_all_kernel(const float* __restrict__ inputs,
                          const float* __restrict__ codebook) {
    const int t = threadIdx.x;
    const int warp = t >> 5, lane = t & 31;
    const int grow = (blockIdx.x << 3) + warp;          // 0 .. 20479
    const bool is_cb = (grow < K_CB);
    const int row = is_cb ? grow : (grow - K_CB);
    const float* src = (is_cb ? codebook : inputs) + (size_t)row * D_DIM + (lane << 3);

    const float4 v0 = ((const float4*)src)[0];
    const float4 v1 = ((const float4*)src)[1];
    float ss = v0.x * v0.x + v0.y * v0.y + v0.z * v0.z + v0.w * v0.w
             + v1.x * v1.x + v1.y * v1.y + v1.z * v1.z + v1.w * v1.w;
    #pragma unroll
    for (int o = 16; o > 0; o >>= 1) ss += __shfl_xor_sync(0xffffffffu, ss, o);

    const float inv = 1.0f / fmaxf(sqrtf(ss), 1e-12f);
    float q[8] = {v0.x * inv, v0.y * inv, v0.z * inv, v0.w * inv,
                  v1.x * inv, v1.y * inv, v1.z * inv, v1.w * inv};
    __nv_bfloat16 h8[8], l8[8];
    #pragma unroll
    for (int i = 0; i < 8; i++) {
        h8[i] = __float2bfloat16(q[i]);
        l8[i] = __float2bfloat16(q[i] - __bfloat162float(h8[i]));
    }
    const size_t off = (size_t)row * D_DIM + (lane << 3);
    float* qdst = (is_cb ? g_cbn : g_xn) + off;
    ((float4*)qdst)[0] = make_float4(q[0], q[1], q[2], q[3]);
    ((float4*)qdst)[1] = make_float4(q[4], q[5], q[6], q[7]);
    *(uint4*)((is_cb ? g_cbh : g_xh) + off) = *(const uint4*)h8;
    *(uint4*)((is_cb ? g_cbl : g_xl) + off) = *(const uint4*)l8;
    if (is_cb && lane == 0) g_counts[row] = 0;
}

// ===================== cp.async pipelined split-bf16 GEMM ==================
// g_logits[m,n] = exp(20*(xh·cbh + xh·cbl + xl·cbh) - 20)
// CTA 128x128, 8 warps (2M x 4N), warp tile 64x32, 3-stage cp.async ring,
// 12 BK=64 chunks (3 phases x 4), ONE sync/iter, 2 CTAs/SM.
#define SA 72
#define TILE_B (128 * SA * 2)
#define STAGE_B (2 * TILE_B)
#define GEMM_SMEM (3 * STAGE_B)

__device__ __forceinline__ void cp16(uint32_t saddr, const void* gptr) {
    asm volatile("cp.async.cg.shared.global [%0], [%1], 16;"
                 :: "r"(saddr), "l"(__cvta_generic_to_global(gptr)));
}

__global__ __launch_bounds__(256, 2)
void gemm_tc_kernel() {
    extern __shared__ char sm[];
    const uint32_t sbase = smem_u32(sm);

    const int t = threadIdx.x;
    const int wid = t >> 5, lane = t & 31;
    const int g = lane >> 2, tig = lane & 3;
    const int warpM = wid & 1;
    const int warpN = wid >> 1;
    const int m0 = blockIdx.y << 7;
    const int n0 = blockIdx.x << 7;

    const int lsel = lane & 15;
    const int ksel = (lane >> 4) << 3;

    float acc[4][4][4];
    #pragma unroll
    for (int i = 0; i < 4; i++)
        #pragma unroll
        for (int j = 0; j < 4; j++)
            #pragma unroll
            for (int c = 0; c < 4; c++) acc[i][j][c] = 0.0f;

    auto issue_stage = [&](int stage, int kt) {
        const int phase = kt >> 2;
        const int d0 = (kt & 3) << 6;
        const __nv_bfloat16* Asrc = (phase == 2) ? g_xl  : g_xh;
        const __nv_bfloat16* Bsrc = (phase == 1) ? g_cbl : g_cbh;
        const uint32_t sa = sbase + stage * STAGE_B;
        const uint32_t sb = sa + TILE_B;
        #pragma unroll
        for (int j = 0; j < 4; j++) {
            const int c = t + (j << 8);
            const int row = c >> 3, sub = c & 7;
            cp16(sa + row * (SA * 2) + sub * 16,
                 Asrc + (size_t)(m0 + row) * D_DIM + d0 + sub * 8);
            cp16(sb + row * (SA * 2) + sub * 16,
                 Bsrc + (size_t)(n0 + row) * D_DIM + d0 + sub * 8);
        }
        asm volatile("cp.async.commit_group;");
    };

    issue_stage(0, 0);
    issue_stage(1, 1);

    #pragma unroll 1
    for (int kt = 0; kt < 12; kt++) {
        if (kt < 11) asm volatile("cp.async.wait_group 1;");
        else         asm volatile("cp.async.wait_group 0;");
        __syncthreads();

        if (kt < 10) {
            const int ns = (kt + 2) - ((kt + 2) / 3) * 3;
            issue_stage(ns, kt + 2);
        }

        const int stage = kt - (kt / 3) * 3;
        const uint32_t sa = sbase + stage * STAGE_B;
        const uint32_t sb = sa + TILE_B;

        #pragma unroll
        for (int k0 = 0; k0 < 64; k0 += 16) {
            uint32_t af[4][4], bfr[4][2];
            #pragma unroll
            for (int mt = 0; mt < 4; mt++) {
                const uint32_t aaddr = sa
                    + (warpM * 64 + mt * 16 + lsel) * (SA * 2) + (k0 + ksel) * 2;
                asm volatile(
                    "ldmatrix.sync.aligned.m8n8.x4.shared.b16 {%0,%1,%2,%3}, [%4];"
                    : "=r"(af[mt][0]), "=r"(af[mt][1]), "=r"(af[mt][2]), "=r"(af[mt][3])
                    : "r"(aaddr));
            }
            #pragma unroll
            for (int np = 0; np < 2; np++) {
                const uint32_t baddr = sb
                    + (warpN * 32 + np * 16 + lsel) * (SA * 2) + (k0 + ksel) * 2;
                asm volatile(
                    "ldmatrix.sync.aligned.m8n8.x4.shared.b16 {%0,%1,%2,%3}, [%4];"
                    : "=r"(bfr[2 * np][0]), "=r"(bfr[2 * np + 1][0]),
                      "=r"(bfr[2 * np][1]), "=r"(bfr[2 * np + 1][1])
                    : "r"(baddr));
            }
            #pragma unroll
            for (int mt = 0; mt < 4; mt++)
                #pragma unroll
                for (int nt = 0; nt < 4; nt++)
                    asm volatile(
                        "mma.sync.aligned.m16n8k16.row.col.f32.bf16.bf16.f32 "
                        "{%0,%1,%2,%3}, {%4,%5,%6,%7}, {%8,%9}, {%0,%1,%2,%3};"
                        : "+f"(acc[mt][nt][0]), "+f"(acc[mt][nt][1]),
                          "+f"(acc[mt][nt][2]), "+f"(acc[mt][nt][3])
                        : "r"(af[mt][0]), "r"(af[mt][1]), "r"(af[mt][2]), "r"(af[mt][3]),
                          "r"(bfr[nt][0]), "r"(bfr[nt][1]));
        }
    }

    // epilogue: exp(20*acc - 20), float2 stores into aligned g_logits
    #pragma unroll
    for (int mt = 0; mt < 4; mt++) {
        #pragma unroll
        for (int nt = 0; nt < 4; nt++) {
            const int r  = m0 + warpM * 64 + mt * 16 + g;
            const int cc = n0 + warpN * 32 + nt * 8 + tig * 2;
            float2 v0, v1;
            v0.x = __expf(fmaf(20.0f, acc[mt][nt][0], -20.0f));
            v0.y = __expf(fmaf(20.0f, acc[mt][nt][1], -20.0f));
            v1.x = __expf(fmaf(20.0f, acc[mt][nt][2], -20.0f));
            v1.y = __expf(fmaf(20.0f, acc[mt][nt][3], -20.0f));
            *(float2*)(g_logits + (size_t)r * K_CB + cc)       = v0;
            *(float2*)(g_logits + (size_t)(r + 8) * K_CB + cc) = v1;
        }
    }
}

// ===================== softmax / argmin / gather ===========================
#define MAX_CAND 64

__global__ __launch_bounds__(256)
void softmax_row_kernel(float* __restrict__ probs,
                        float* __restrict__ quant,
                        float* __restrict__ idx_out) {
    __shared__ float  xrow[256];
    __shared__ float  shm[8], shs[8];
    __shared__ double shd8[8];
    __shared__ int    cand[MAX_CAND];
    __shared__ double cdist[MAX_CAND];
    __shared__ int    ncand;
    __shared__ int    ridx_sh;

    const int n = blockIdx.x, t = threadIdx.x;
    const float* lrow = g_logits + (size_t)n * K_CB;   // already exp()
    float* prow = probs + (size_t)n * K_CB;

    xrow[t] = g_xn[n * D_DIM + t];
    if (t == 0) ncand = 0;

    float ev[16];
    float emax = 0.0f, esum = 0.0f;
    #pragma unroll
    for (int i = 0; i < 4; i++) {
        const float4 v = *(const float4*)(lrow + (t << 2) + (i << 10));
        ev[4 * i + 0] = v.x; ev[4 * i + 1] = v.y;
        ev[4 * i + 2] = v.z; ev[4 * i + 3] = v.w;
        emax = fmaxf(fmaxf(fmaxf(v.x, v.y), fmaxf(v.z, v.w)), emax);
        esum += (v.x + v.y) + (v.z + v.w);
    }
    float evmax, tot;
    block_reduce_maxsum256(emax, esum, shm, shs, &evmax, &tot);

    const float inv = 1.0f / tot;
    #pragma unroll
    for (int i = 0; i < 16; i++)
        prow[(t << 2) + ((i >> 2) << 10) + (i & 3)] = ev[i] * inv;

    const float cthresh = evmax * 0.999f;
    #pragma unroll
    for (int i = 0; i < 16; i++) {
        if (ev[i] >= cthresh) {
            const int p = atomicAdd(&ncand, 1);
            if (p < MAX_CAND) cand[p] = (t << 2) + ((i >> 2) << 10) + (i & 3);
        }
    }
    __syncthreads();
    const int nc = min(ncand, MAX_CAND);

    for (int c = 0; c < nc; c++) {
        const int k = cand[c];
        const double prod = (double)xrow[t] * (double)g_cbn[(size_t)k * D_DIM + t];
        const double s = block_reduce_sum256_d(prod, shd8);
        if (t == 0) cdist[c] = 2.0 - 2.0 * s;
    }
    __syncthreads();

    if (t == 0) {
        double dmin = 1e30;
        for (int c = 0; c < nc; c++) dmin = fmin(dmin, cdist[c]);
        int bi = 0x7fffffff;
        for (int c = 0; c < nc; c++)
            if (cdist[c] <= dmin + 4e-7) bi = min(bi, cand[c]);
        ridx_sh = bi;
    }
    __syncthreads();

    const int ridx = ridx_sh;
    const float xv = xrow[t];
    const float cv = g_cbn[(size_t)ridx * D_DIM + t];
    quant[(size_t)n * D_DIM + t] = xv + (cv - xv);
    const float d = cv - xv;
    const float lp = block_reduce_sum256(d * d, shm);
    if (t == 0) {
        g_loss_partial[n] = lp;
        atomicAdd(&g_counts[ridx], 1);
        idx_out[n] = (float)ridx;
    }
}

// ===================== finalize ============================================
__global__ __launch_bounds__(1024)
void finalize_kernel(float* __restrict__ out_loss,
                     float* __restrict__ out_perp) {
    __shared__ float sh32[32];
    const int t = threadIdx.x;
    float s = 0.0f;
    #pragma unroll
    for (int i = 0; i < 4; i++) {
        const float4 v = *(const float4*)(g_loss_partial + (t << 2) + (i << 12));
        s += (v.x + v.y) + (v.z + v.w);
    }
    const float tot = block_reduce_sum1024(s, sh32);

    float e = 0.0f;
    const int4 cv = *(const int4*)(g_counts + (t << 2));
    const float invN = 1.0f / (float)N_ROWS;
    {
        const float p0 = (float)cv.x * invN, p1 = (float)cv.y * invN;
        const float p2 = (float)cv.z * invN, p3 = (float)cv.w * invN;
        e = p0 * logf(p0 + 1e-10f) + p1 * logf(p1 + 1e-10f)
          + p2 * logf(p2 + 1e-10f) + p3 * logf(p3 + 1e-10f);
    }
    const float esum = block_reduce_sum1024(e, sh32);

    if (t == 0) {
        *out_loss = 0.25f * (tot / (float)((size_t)N_ROWS * D_DIM));
        *out_perp = expf(-esum);
    }
}

// ===========================================================================
extern "C" void kernel_launch(void* const* d_in, const int* in_sizes, int n_in,
                              void* d_out, int out_size) {
    const float* inputs   = (const float*)d_in[0];
    const float* codebook = (const float*)d_in[1];

    float* out       = (float*)d_out;
    float* out_loss  = out;
    float* out_quant = out + 1;
    float* out_probs = out_quant + (size_t)N_ROWS * D_DIM;
    float* out_perp  = out_probs + (size_t)N_ROWS * K_CB;
    float* out_idx   = out_perp + 1;

    cudaFuncSetAttribute(gemm_tc_kernel,
                         cudaFuncAttributeMaxDynamicSharedMemorySize, GEMM_SMEM);

    normalize_all_kernel<<<(K_CB + N_ROWS) / 8, 256>>>(inputs, codebook);

    dim3 grid(K_CB / 128, N_ROWS / 128);   // (32, 128)
    gemm_tc_kernel<<<grid, 256, GEMM_SMEM>>>();

    softmax_row_kernel<<<N_ROWS, 256>>>(out_probs, out_quant, out_idx);
    finalize_kernel<<<1, 1024>>>(out_loss, out_perp);
}